// round 3
// baseline (speedup 1.0000x reference)
#include <cuda_runtime.h>

// MaxAssigner2D, two-phase:
//   Phase 1 (streaming): xc[p] = max over 32 channels of x[p*32 .. p*32+31]
//   Phase 2 (stencil):   out[b,h,w] = max over taps
//       {(0,0),(-1,0),(-2,0),(0,-1),(0,-2),(-1,-1),(-2,-2)} of xc[b,h+dh,w+dw]
//   (out-of-image taps contribute 0, matching the reference zero pad)

#define BATCH 16
#define HGT   512
#define WID   512
#define CH    32
#define NPIX  (BATCH * HGT * WID)   // 4,194,304

__device__ float g_xc[NPIX];        // 16 MB scratch (allocation-free)

// ---------------- Phase 1: channel-max, pure streaming ----------------
#define K1_NT      256
#define K1_BLOCKS  2048
#define K1_GROUPS  (K1_BLOCKS * K1_NT / 8)        // 65,536 pixel groups / sweep
#define K1_ITERS   (NPIX / K1_GROUPS)             // 64, exact

__global__ void __launch_bounds__(K1_NT)
chanmax_kernel(const float* __restrict__ x)
{
    const int tid = blockIdx.x * K1_NT + threadIdx.x;
    const int gid = tid >> 3;           // pixel-group id
    const int chq = tid & 7;            // which float4 of 32 channels

    #pragma unroll 8
    for (int it = 0; it < K1_ITERS; it++) {
        const int p = it * K1_GROUPS + gid;
        const float4 d = __ldg((const float4*)(x + (size_t)p * CH) + chq);
        float v = fmaxf(fmaxf(d.x, d.y), fmaxf(d.z, d.w));
        v = fmaxf(v, __shfl_xor_sync(0xffffffffu, v, 1));
        v = fmaxf(v, __shfl_xor_sync(0xffffffffu, v, 2));
        v = fmaxf(v, __shfl_xor_sync(0xffffffffu, v, 4));
        if (chq == 0) g_xc[p] = v;
    }
}

// ---------------- Phase 2: register-rolling 7-tap stencil ----------------
// Warp owns 32 consecutive columns, sweeps TH rows. One coalesced load per
// warp-row; c-1/c-2 taps via shfl_up (lanes 0,1 patch via direct loads);
// h-1/h-2 taps via rotating registers. No smem, no barriers.
#define TH2    32
#define K2_NT  256                    // 8 warps = 256 columns per block
#define K2_COLT (WID / K2_NT)         // 2 column tiles
#define K2_STRIPS (HGT / TH2)         // 16 row strips

__device__ __forceinline__ void load_xc_row(const float* __restrict__ xc,
                                            int g, int c, int lane,
                                            float& a, float& l1, float& l2)
{
    if (g >= 0) {
        const float* row = xc + (size_t)g * WID;
        a  = __ldg(row + c);
        l1 = __shfl_up_sync(0xffffffffu, a, 1);
        l2 = __shfl_up_sync(0xffffffffu, a, 2);
        if (lane == 0) l1 = (c >= 1) ? __ldg(row + c - 1) : 0.0f;
        if (lane <  2) l2 = (c >= 2) ? __ldg(row + c - 2) : 0.0f;
    } else {
        a = 0.0f; l1 = 0.0f; l2 = 0.0f;
    }
}

__global__ void __launch_bounds__(K2_NT)
stencil_kernel(float* __restrict__ out)
{
    const int lane = threadIdx.x & 31;
    const int warp = threadIdx.x >> 5;

    // blockIdx.x in [0, 16*16*2): img / strip / column-tile
    const int b     = blockIdx.x;
    const int img   = b / (K2_STRIPS * K2_COLT);
    const int rem   = b % (K2_STRIPS * K2_COLT);
    const int strip = rem >> 1;
    const int tile  = rem & 1;

    const int c    = tile * K2_NT + warp * 32 + lane;
    const int row0 = strip * TH2;
    const float* xc = g_xc + (size_t)img * HGT * WID;

    // Preamble: rows row0-2 (need a, c-2) and row0-1 (need a, c-1)
    float r2a, r2l1, r2l2, r1a, r1l1, r1l2;
    load_xc_row(xc, row0 - 2, c, lane, r2a, r2l1, r2l2);
    load_xc_row(xc, row0 - 1, c, lane, r1a, r1l1, r1l2);

    float* optr = out + (((size_t)img * HGT + row0) * WID + c);

    #pragma unroll 4
    for (int r = 0; r < TH2; r++) {
        float a, l1, l2;
        load_xc_row(xc, row0 + r, c, lane, a, l1, l2);

        float m = fmaxf(a, fmaxf(l1, l2));        // (0,0) (0,-1) (0,-2)
        m = fmaxf(m, fmaxf(r1a, r1l1));           // (-1,0) (-1,-1)
        m = fmaxf(m, fmaxf(r2a, r2l2));           // (-2,0) (-2,-2)
        optr[(size_t)r * WID] = m;

        r2a = r1a; r2l1 = r1l1; r2l2 = r1l2;      // rotate rows
        r1a = a;   r1l1 = l1;   r1l2 = l2;
    }
}

extern "C" void kernel_launch(void* const* d_in, const int* in_sizes, int n_in,
                              void* d_out, int out_size)
{
    (void)in_sizes; (void)n_in; (void)out_size;
    const float* x = (const float*)d_in[0];
    float* out = (float*)d_out;

    chanmax_kernel<<<K1_BLOCKS, K1_NT>>>(x);
    stencil_kernel<<<BATCH * K2_STRIPS * K2_COLT, K2_NT>>>(out);
}

// round 4
// speedup vs baseline: 1.0437x; 1.0437x over previous
#include <cuda_runtime.h>

// MaxAssigner2D, two-phase:
//   Phase 1 (streaming): xc[p] = max over 32 channels of x[p*32 .. p*32+31]
//   Phase 2 (stencil):   out[b,h,w] = max over taps
//       {(0,0),(-1,0),(-2,0),(0,-1),(0,-2),(-1,-1),(-2,-2)} of xc[b,h+dh,w+dw]
//   (out-of-image taps contribute 0, matching the reference zero pad)

#define BATCH 16
#define HGT   512
#define WID   512
#define CH    32
#define NPIX  (BATCH * HGT * WID)   // 4,194,304

__device__ float g_xc[NPIX];        // 16 MB scratch (allocation-free)

// ---------------- Phase 1: channel-max, pure streaming ----------------
// 8 lanes per pixel: one coalesced 16B load each (512B contiguous per warp),
// shfl-xor reduce over the 8-lane group. __ldcs: x is read exactly once ->
// evict-first, keep L2 free so xc stays resident for phase 2.
#define K1_NT      256
#define K1_BLOCKS  2048
#define K1_GROUPS  (K1_BLOCKS * K1_NT / 8)        // 65,536 pixel groups / sweep
#define K1_ITERS   (NPIX / K1_GROUPS)             // 64, exact

__global__ void __launch_bounds__(K1_NT)
chanmax_kernel(const float* __restrict__ x)
{
    const int tid = blockIdx.x * K1_NT + threadIdx.x;
    const int gid = tid >> 3;           // pixel-group id
    const int chq = tid & 7;            // which float4 of 32 channels

    #pragma unroll 8
    for (int it = 0; it < K1_ITERS; it++) {
        const int p = it * K1_GROUPS + gid;
        const float4 d = __ldcs((const float4*)(x + (size_t)p * CH) + chq);
        float v = fmaxf(fmaxf(d.x, d.y), fmaxf(d.z, d.w));
        v = fmaxf(v, __shfl_xor_sync(0xffffffffu, v, 1));
        v = fmaxf(v, __shfl_xor_sync(0xffffffffu, v, 2));
        v = fmaxf(v, __shfl_xor_sync(0xffffffffu, v, 4));
        if (chq == 0) g_xc[p] = v;
    }
}

// ---------------- Phase 2: 7-tap stencil on xc (smem tile) ----------------
#define TH    16
#define HALO  2
#define TROWS (TH + HALO)        // 18
#define SW    (WID + HALO)       // 514
#define K2_NT 512

__global__ void __launch_bounds__(K2_NT)
stencil_kernel(float* __restrict__ out)
{
    __shared__ float s[TROWS * SW];    // 37,008 B

    const int tid  = threadIdx.x;
    const int img  = blockIdx.x / (HGT / TH);
    const int tile = blockIdx.x % (HGT / TH);
    const int row0 = tile * TH;

    // zero the 2 left-halo columns
    if (tid < TROWS * HALO) {
        int r = tid / HALO, c = tid % HALO;
        s[r * SW + c] = 0.0f;
    }

    // Fill: 18 rows x 512 cols via float4 (128 float4 per row).
    // Thread layout: q = tid & 127 selects the float4 within a row,
    // r = tid >> 7 strides over rows by 4. All loads independent -> high MLP.
    {
        const int q  = tid & 127;
        const int r0 = tid >> 7;
        const float* xc_img = g_xc + (size_t)img * HGT * WID;
        #pragma unroll
        for (int r = r0; r < TROWS; r += 4) {
            const int g = row0 + r - HALO;
            float4 v = make_float4(0.f, 0.f, 0.f, 0.f);
            if (g >= 0)
                v = __ldg((const float4*)(xc_img + (size_t)g * WID) + q);
            float* dst = s + r * SW + HALO + q * 4;
            dst[0] = v.x; dst[1] = v.y; dst[2] = v.z; dst[3] = v.w;
        }
    }
    __syncthreads();

    float* orow = out + (((size_t)img * HGT + row0) * WID + tid);
    #pragma unroll
    for (int r = 0; r < TH; r++) {
        const float* s0 = s + r * SW + tid;   // row (h-2)
        const float* s1 = s0 + SW;            // row (h-1)
        const float* s2 = s1 + SW;            // row (h)
        float m = s2[HALO];                   // ( 0, 0)
        m = fmaxf(m, s1[HALO]);               // (-1, 0)
        m = fmaxf(m, s0[HALO]);               // (-2, 0)
        m = fmaxf(m, s2[HALO - 1]);           // ( 0,-1)
        m = fmaxf(m, s2[HALO - 2]);           // ( 0,-2)
        m = fmaxf(m, s1[HALO - 1]);           // (-1,-1)
        m = fmaxf(m, s0[HALO - 2]);           // (-2,-2)
        orow[(size_t)r * WID] = m;
    }
}

extern "C" void kernel_launch(void* const* d_in, const int* in_sizes, int n_in,
                              void* d_out, int out_size)
{
    (void)in_sizes; (void)n_in; (void)out_size;
    const float* x = (const float*)d_in[0];
    float* out = (float*)d_out;

    chanmax_kernel<<<K1_BLOCKS, K1_NT>>>(x);
    stencil_kernel<<<BATCH * (HGT / TH), K2_NT>>>(out);
}